// round 3
// baseline (speedup 1.0000x reference)
#include <cuda_runtime.h>
#include <cuda_bf16.h>
#include <math.h>

// FFMCell: new_state = state * gamma(t) + x, gamma = exp((-|a| + i b) * t)
// T=4096, TRACE=64, CTX=64.
//
// R3: two kernels.
//   1) table_kernel: dec[t][tr] = exp(-|a|*t), cs[t][c] = (cos(b*t), sin(b*t))
//      into __device__ scratch (3 MB). Also writes the (j+i) tail.
//   2) hot_kernel: pure streaming, 1 float4-group per thread, no smem/barrier/
//      MUFU, ~35 regs -> 75% occupancy. Inputs via __ldcs (evict-first) so the
//      table stays L2/L1 resident.

#define TMAX 4096
#define KDIM 64

__device__ float  g_dec[TMAX * KDIM];
__device__ float2 g_cs [TMAX * KDIM];

__global__ void table_kernel(const float* __restrict__ a,
                             const float* __restrict__ b,
                             const int* __restrict__ iv,
                             const int* __restrict__ jv,
                             float* __restrict__ tail,
                             int total)
{
    const int idx = blockIdx.x * blockDim.x + threadIdx.x;
    if (idx >= total) return;
    const int t = idx >> 6;
    const int k = idx & 63;

    const float tf = (float)__ldg(&jv[t]);

    g_dec[idx] = expf(-fabsf(__ldg(&a[k])) * tf);

    const float th = __ldg(&b[k]) * tf;   // same fp32 product as reference
    float sn, cs;
    sincosf(th, &sn, &cs);
    g_cs[idx] = make_float2(cs, sn);

    if (k == 0 && tail != nullptr) {
        tail[t] = (float)(__ldg(&jv[t]) + __ldg(&iv[t]));
    }
}

__global__ void __launch_bounds__(256, 6) hot_kernel(
    const float4* __restrict__ sre,
    const float4* __restrict__ sim,
    const float4* __restrict__ xre,
    const float4* __restrict__ xim,
    float4* __restrict__ out4,
    long long ngroups)
{
    const long long g = (long long)blockIdx.x * blockDim.x + threadIdx.x;
    if (g >= ngroups) return;

    // 4 big streaming loads, front-batched
    const float4 sr = __ldcs(&sre[g]);
    const float4 si = __ldcs(&sim[g]);
    const float4 xr = __ldcs(&xre[g]);
    const float4 xi = __ldcs(&xim[g]);

    // table lookups (L1-resident: dec reused 16x, cs lines reused 64x)
    const float dec = __ldg(&g_dec[g >> 4]);
    const float4* __restrict__ cs4 = reinterpret_cast<const float4*>(g_cs);
    const long long ci = ((g >> 10) << 5) + ((g & 15) << 1);
    const float4 csA = __ldg(&cs4[ci]);       // (cos0, sin0, cos1, sin1)
    const float4 csB = __ldg(&cs4[ci + 1]);   // (cos2, sin2, cos3, sin3)

    const float gr0 = dec * csA.x, gi0 = dec * csA.y;
    const float gr1 = dec * csA.z, gi1 = dec * csA.w;
    const float gr2 = dec * csB.x, gi2 = dec * csB.y;
    const float gr3 = dec * csB.z, gi3 = dec * csB.w;

    float4 o0, o1;
    o0.x = fmaf(sr.x, gr0, fmaf(-si.x, gi0, xr.x));
    o0.y = fmaf(sr.x, gi0, fmaf( si.x, gr0, xi.x));
    o0.z = fmaf(sr.y, gr1, fmaf(-si.y, gi1, xr.y));
    o0.w = fmaf(sr.y, gi1, fmaf( si.y, gr1, xi.y));
    o1.x = fmaf(sr.z, gr2, fmaf(-si.z, gi2, xr.z));
    o1.y = fmaf(sr.z, gi2, fmaf( si.z, gr2, xi.z));
    o1.z = fmaf(sr.w, gr3, fmaf(-si.w, gi3, xr.w));
    o1.w = fmaf(sr.w, gi3, fmaf( si.w, gr3, xi.w));

    out4[2 * g]     = o0;
    out4[2 * g + 1] = o1;
}

extern "C" void kernel_launch(void* const* d_in, const int* in_sizes, int n_in,
                              void* d_out, int out_size)
{
    const float4* sre = (const float4*)d_in[0];
    const float4* sim = (const float4*)d_in[1];
    const float4* xre = (const float4*)d_in[2];
    const float4* xim = (const float4*)d_in[3];
    const float*  a   = (const float*)d_in[4];
    const float*  b   = (const float*)d_in[5];
    const int*    iv  = (const int*)d_in[6];
    const int*    jv  = (const int*)d_in[7];

    const int T = in_sizes[6];                      // 4096
    const long long N = (long long)in_sizes[0];     // T*TRACE*CTX

    float* out = (float*)d_out;
    float* out_tail = nullptr;
    if ((long long)out_size > 2LL * N) {
        out_tail = out + 2LL * N;
    }

    // 1) factor table (+ tail)
    int total = T * KDIM;
    if (total > TMAX * KDIM) total = TMAX * KDIM;
    table_kernel<<<(total + 255) / 256, 256>>>(a, b, iv, jv, out_tail, total);

    // 2) streaming hot kernel
    const long long ngroups = N / 4;
    const int blocks = (int)((ngroups + 255) / 256);
    hot_kernel<<<blocks, 256>>>(sre, sim, xre, xim,
                                reinterpret_cast<float4*>(out), ngroups);
}

// round 4
// speedup vs baseline: 1.0163x; 1.0163x over previous
#include <cuda_runtime.h>
#include <cuda_bf16.h>
#include <math.h>

// FFMCell: new_state = state * gamma(t) + x, gamma = exp((-|a| + i b) * t)
// T=4096, TRACE=64, CTX=64.
//
// R4: single fused kernel. Grid = 4*T blocks, 256 threads; each block covers
// 1024 contiguous elements (16 trace rows x 64 ctx of one t-tile). Each
// thread front-batches its 4 streaming LDG.128s, then a small subset of
// threads computes the per-block gamma factors (16 expf + 64 sincosf) into
// smem, one barrier, then FMA + 2 STG.128. Low regs -> ~75% occupancy, so
// barrier/MUFU latency is covered by co-resident blocks.

__global__ void __launch_bounds__(256, 6) ffm_fused_kernel(
    const float4* __restrict__ sre,
    const float4* __restrict__ sim,
    const float4* __restrict__ xre,
    const float4* __restrict__ xim,
    const float* __restrict__ a,
    const float* __restrict__ b,
    const int* __restrict__ ivec,
    const int* __restrict__ jvec,
    float* __restrict__ out,
    float* __restrict__ out_tail)
{
    const int bid = blockIdx.x;
    const int tid = threadIdx.x;
    const int t   = bid >> 2;               // t-tile index
    const int qb  = (bid & 3) << 4;         // first trace row of this block

    __shared__ float  s_dec[16];
    __shared__ float2 s_cs[64];             // (cos, sin) per ctx

    // ---- Phase 0: front-batch the 4 streaming loads ---------------------
    const long long g = (long long)bid * 256 + tid;   // float4-group index
    const float4 sr = __ldcs(&sre[g]);
    const float4 si = __ldcs(&sim[g]);
    const float4 xr = __ldcs(&xre[g]);
    const float4 xi = __ldcs(&xim[g]);

    // ---- Phase 1: per-block factors (overlaps with loads in flight) -----
    const float tf = (float)__ldg(&jvec[t]);

    if (tid < 16) {
        s_dec[tid] = expf(-fabsf(__ldg(&a[qb + tid])) * tf);
    } else if (tid >= 64 && tid < 128) {
        const int c = tid - 64;
        const float th = __ldg(&b[c]) * tf;  // same fp32 product as reference
        float sn, cs;
        sincosf(th, &sn, &cs);
        s_cs[c] = make_float2(cs, sn);
    } else if (tid == 160 && (bid & 3) == 0 && out_tail != nullptr) {
        out_tail[t] = (float)(__ldg(&jvec[t]) + __ldg(&ivec[t]));
    }
    __syncthreads();

    // ---- Phase 2: compute + store ---------------------------------------
    const int tr = tid >> 4;                 // 0..15 (local trace row)
    const int c2 = (tid & 15) << 1;          // float4 index into s_cs pairs

    const float dec = s_dec[tr];
    const float4* s_cs4 = reinterpret_cast<const float4*>(s_cs);
    const float4 csA = s_cs4[c2];            // (cos0,sin0,cos1,sin1)
    const float4 csB = s_cs4[c2 + 1];        // (cos2,sin2,cos3,sin3)

    const float gr0 = dec * csA.x, gi0 = dec * csA.y;
    const float gr1 = dec * csA.z, gi1 = dec * csA.w;
    const float gr2 = dec * csB.x, gi2 = dec * csB.y;
    const float gr3 = dec * csB.z, gi3 = dec * csB.w;

    float4 o0, o1;
    o0.x = fmaf(sr.x, gr0, fmaf(-si.x, gi0, xr.x));
    o0.y = fmaf(sr.x, gi0, fmaf( si.x, gr0, xi.x));
    o0.z = fmaf(sr.y, gr1, fmaf(-si.y, gi1, xr.y));
    o0.w = fmaf(sr.y, gi1, fmaf( si.y, gr1, xi.y));
    o1.x = fmaf(sr.z, gr2, fmaf(-si.z, gi2, xr.z));
    o1.y = fmaf(sr.z, gi2, fmaf( si.z, gr2, xi.z));
    o1.z = fmaf(sr.w, gr3, fmaf(-si.w, gi3, xr.w));
    o1.w = fmaf(sr.w, gi3, fmaf( si.w, gr3, xi.w));

    float4* __restrict__ out4 = reinterpret_cast<float4*>(out);
    out4[2 * g]     = o0;
    out4[2 * g + 1] = o1;
}

extern "C" void kernel_launch(void* const* d_in, const int* in_sizes, int n_in,
                              void* d_out, int out_size)
{
    const float4* sre = (const float4*)d_in[0];
    const float4* sim = (const float4*)d_in[1];
    const float4* xre = (const float4*)d_in[2];
    const float4* xim = (const float4*)d_in[3];
    const float*  a   = (const float*)d_in[4];
    const float*  b   = (const float*)d_in[5];
    const int*    iv  = (const int*)d_in[6];
    const int*    jv  = (const int*)d_in[7];

    const int T = in_sizes[6];                      // 4096
    const long long N = (long long)in_sizes[0];     // T*TRACE*CTX

    float* out = (float*)d_out;
    float* out_tail = nullptr;
    if ((long long)out_size > 2LL * N) {
        out_tail = out + 2LL * N;
    }

    ffm_fused_kernel<<<4 * T, 256>>>(sre, sim, xre, xim, a, b, iv, jv,
                                     out, out_tail);
}